// round 11
// baseline (speedup 1.0000x reference)
#include <cuda_runtime.h>
#include <cuda_bf16.h>
#include <cstdint>

// ---------------- problem constants ----------------
#define NB     64
#define CINC   256
#define COUTC  256
#define CSC    256
#define HIDC   64
#define LDIMC  1024
#define TEMPR  30.0f

// ---------------- GEMM tiling ----------------
#define BM   64           // o per block (4 o-tiles)
#define BN   128          // l per block (8 l-tiles)
#define IC   16           // input channels per chunk
#define NCH  16           // CINC / IC

// ---------------- gemm smem map (dynamic) ----------------
// [0,256)           : aggregated bias (64 floats)
// [512, +2*12288)   : A stages; each = 6 tiles (tap x hi/lo) of 64 rows x 48B...
//                     (tile = 64 rows x 32B data padded into 48B-pitch rows)
// [25088, +2*12480) : X stages; each = hi(130x48B) + lo(130x48B)
#define OFF_A   512
#define ATILE   2048      // bytes per A tile (64 rows x 16 ch x 2B)
#define ASTB    12288     // A stage stride (6 tiles)
#define OFF_X   25088
#define XST     12480
#define SMEMSZ  50048

// ---------------- device scratch ----------------
__device__ float g_att[NB * 4];
// aggregated weights pre-swizzled into gemm consumption order:
// [b][ot(4)][ic(16)][tap(3)][hl(2)][row(64)][ch(16)] bf16
__device__ __align__(16) __nv_bfloat16 g_w[(size_t)NB * 4 * 16 * 6 * 1024];

// ---------------- helpers ----------------
__device__ __forceinline__ uint32_t smem_u32(const void* p) {
    uint32_t a;
    asm("{ .reg .u64 t; cvta.to.shared.u64 t, %1; cvt.u32.u64 %0, t; }" : "=r"(a) : "l"(p));
    return a;
}
__device__ __forceinline__ void ldsm4(uint32_t (&r)[4], uint32_t addr) {
    asm volatile("ldmatrix.sync.aligned.m8n8.x4.shared.b16 {%0,%1,%2,%3}, [%4];"
                 : "=r"(r[0]), "=r"(r[1]), "=r"(r[2]), "=r"(r[3]) : "r"(addr));
}
__device__ __forceinline__ void mma16816(float (&d)[4], const uint32_t (&a)[4],
                                         const uint32_t (&b)[2]) {
    asm volatile(
        "mma.sync.aligned.m16n8k16.row.col.f32.bf16.bf16.f32 "
        "{%0,%1,%2,%3}, {%4,%5,%6,%7}, {%8,%9}, {%0,%1,%2,%3};"
        : "+f"(d[0]), "+f"(d[1]), "+f"(d[2]), "+f"(d[3])
        : "r"(a[0]), "r"(a[1]), "r"(a[2]), "r"(a[3]), "r"(b[0]), "r"(b[1]));
}
__device__ __forceinline__ uint32_t pack_hi(float v0, float v1) {
    uint32_t hp;
    asm("cvt.rn.bf16x2.f32 %0, %1, %2;" : "=r"(hp) : "f"(v1), "f"(v0));
    return hp;
}
__device__ __forceinline__ void cp_async16(uint32_t dst, const void* src) {
    asm volatile("cp.async.cg.shared.global [%0], [%1], 16;" :: "r"(dst), "l"(src));
}
#define CP_COMMIT() asm volatile("cp.async.commit_group;" ::: "memory")
#define CP_WAIT0()  asm volatile("cp.async.wait_group 0;" ::: "memory")

// ---------------------------------------------------------------------------
// Kernel 1: routing MLP + softmax -> g_att.
// w1 staged through smem once (one coalesced burst) to kill the serial LDG
// waves that made this kernel latency-bound.
// ---------------------------------------------------------------------------
__global__ __launch_bounds__(256) void att_kernel(const float* __restrict__ cond,
                                                  const float* __restrict__ w1,
                                                  const float* __restrict__ w2) {
    extern __shared__ float sm[];
    float* w1s    = sm;            // 16384 floats (64 KB)
    float* sc     = sm + 16384;    // 256
    float* h      = sc + 256;      // 64
    float* logits = h + 64;        // 4

    int b = blockIdx.x;
    int tid = threadIdx.x;
    int w = tid >> 5, l = tid & 31;

    #pragma unroll
    for (int j = 0; j < 16; j++)
        ((float4*)w1s)[tid + 256 * j] = __ldg((const float4*)w1 + tid + 256 * j);
    sc[tid] = cond[b * CSC + tid];
    __syncthreads();

    #pragma unroll
    for (int jj = 0; jj < 8; jj++) {
        int j = w * 8 + jj;
        const float* r = w1s + j * CSC;
        float a = 0.f;
        #pragma unroll
        for (int q = 0; q < 8; q++) a = fmaf(r[l + 32 * q], sc[l + 32 * q], a);
        #pragma unroll
        for (int off = 16; off >= 1; off >>= 1)
            a += __shfl_xor_sync(0xFFFFFFFFu, a, off);
        if (l == 0) h[j] = fmaxf(a, 0.f);
    }
    __syncthreads();

    if (w == 0) {
        #pragma unroll
        for (int j = 0; j < 4; j++) {
            float a = fmaf(__ldg(w2 + j * HIDC + l), h[l],
                           __ldg(w2 + j * HIDC + 32 + l) * h[32 + l]);
            #pragma unroll
            for (int off = 16; off >= 1; off >>= 1)
                a += __shfl_xor_sync(0xFFFFFFFFu, a, off);
            if (l == 0) logits[j] = a / TEMPR;
        }
        __syncwarp();
        if (l == 0) {
            float m = fmaxf(fmaxf(logits[0], logits[1]), fmaxf(logits[2], logits[3]));
            float e[4]; float ssum = 0.f;
            #pragma unroll
            for (int k = 0; k < 4; k++) { e[k] = expf(logits[k] - m); ssum += e[k]; }
            float inv = 1.f / ssum;
            #pragma unroll
            for (int k = 0; k < 4; k++) g_att[b * 4 + k] = e[k] * inv;
        }
    }
}

// ---------------------------------------------------------------------------
// Kernel 2: expert aggregation -> g_w (hi + residual bf16), pre-swizzled.
// Thread owns (t, icc, o, half) = 8 consecutive input channels of one
// (tap, out-channel); weights read ONCE (3.1 MB); per-sample stores are
// 16B per lane, fully coalesced (512B per warp).
// ---------------------------------------------------------------------------
__global__ __launch_bounds__(256) void agg_kernel(const float* __restrict__ weight) {
    __shared__ float satt[NB * 4];
    int tid = threadIdx.x;
    satt[tid] = g_att[tid];   // 256 == NB*4
    __syncthreads();

    int u = blockIdx.x * 256 + tid;     // 0 .. 24575 = 3*16*256*2
    int t   = u >> 13;                  // 0..2
    int r   = u & 8191;
    int icc = r >> 9;                   // 0..15
    int r2  = r & 511;
    int o   = r2 >> 1;                  // 0..255
    int half = r2 & 1;
    int i0  = icc * 16 + half * 8;
    int ot  = o >> 6, row = o & 63;

    float w[8][4];
    const size_t es = (size_t)COUTC * CINC * 9;
    #pragma unroll
    for (int ii = 0; ii < 8; ii++) {
        size_t base = ((size_t)o * CINC + i0 + ii) * 9 + t * 3 + 1;
        #pragma unroll
        for (int e = 0; e < 4; e++) w[ii][e] = __ldg(weight + base + (size_t)e * es);
    }

    for (int b = 0; b < NB; b++) {
        float a0 = satt[b * 4 + 0], a1 = satt[b * 4 + 1];
        float a2 = satt[b * 4 + 2], a3 = satt[b * 4 + 3];
        float v[8];
        #pragma unroll
        for (int ii = 0; ii < 8; ii++)
            v[ii] = fmaf(a3, w[ii][3], fmaf(a2, w[ii][2],
                    fmaf(a1, w[ii][1], a0 * w[ii][0])));
        uint32_t hp[4], lp[4];
        #pragma unroll
        for (int p = 0; p < 4; p++) {
            float f0 = v[2 * p], f1 = v[2 * p + 1];
            hp[p] = pack_hi(f0, f1);
            float h0 = __uint_as_float(hp[p] << 16);
            float h1 = __uint_as_float(hp[p] & 0xFFFF0000u);
            lp[p] = pack_hi(f0 - h0, f1 - h1);
        }
        // tile = tap*2 + hl; tile elems = 64 rows x 16 ch = 1024
        size_t base2 = (((size_t)(b * 4 + ot) * 16 + icc) * 6 + t * 2) * 1024
                     + row * 16 + half * 8;
        *(uint4*)&g_w[base2]        = make_uint4(hp[0], hp[1], hp[2], hp[3]);
        *(uint4*)&g_w[base2 + 1024] = make_uint4(lp[0], lp[1], lp[2], lp[3]);
    }
}

// ---------------------------------------------------------------------------
// Kernel 3: batched GEMM via mma.sync m16n8k16 bf16 (hi/lo compensated).
// Block 64(o) x 128(l); 8 warps as 2(m) x 4(n), warp tile 32x32.
// 2048 blocks -> 6.92 waves on 296 slots (tail 1.2%).  acc=32 regs: no spills
// at 2 CTAs/SM.  Double-buffered A (cp.async, coalesced) + X (reg-prefetched).
// ---------------------------------------------------------------------------
__global__ __launch_bounds__(256, 2)
void gemm_kernel(const float* __restrict__ x,
                 const float* __restrict__ bias,
                 float* __restrict__ out) {
    extern __shared__ char smem[];
    const int tid  = threadIdx.x;
    const int lane = tid & 31, wid = tid >> 5;
    const int wm = wid & 1, wn = wid >> 1;
    const int bq = blockIdx.y;
    const int ot = blockIdx.x & 3;
    const int o0 = ot * BM;
    const int l0 = (blockIdx.x >> 2) * BN;
    const uint32_t sb = smem_u32(smem);

    if (tid < BM) {
        float a0 = g_att[bq * 4 + 0], a1 = g_att[bq * 4 + 1];
        float a2 = g_att[bq * 4 + 2], a3 = g_att[bq * 4 + 3];
        int o = o0 + tid;
        ((float*)smem)[tid] =
            fmaf(a3, bias[3 * COUTC + o], fmaf(a2, bias[2 * COUTC + o],
            fmaf(a1, bias[1 * COUTC + o], a0 * bias[o])));
    }

    float acc[2][4][4];
    #pragma unroll
    for (int mf = 0; mf < 2; mf++)
        #pragma unroll
        for (int nf = 0; nf < 4; nf++)
            #pragma unroll
            for (int q = 0; q < 4; q++) acc[mf][nf][q] = 0.f;

    const uint32_t aro = (lane & 7) + ((lane >> 3) & 1) * 8;
    const uint32_t ako = (lane >> 4) * 16;
    const uint32_t bro = (lane & 7) + ((lane >> 4) & 1) * 8;
    const uint32_t bko = ((lane >> 3) & 1) * 16;

    const float* xb = x + (size_t)bq * CINC * LDIMC;
    // per-(b, ot) weight slab: 16 chunks x 12288 B
    const char* wslab = (const char*)g_w + (size_t)(bq * 4 + ot) * 16 * ASTB;
    const int ipg = tid >> 5;   // x-fill: i-pair (0..7)
    const int lng = tid & 31;   // x-fill: lane -> l

    float xr[5][2];

    auto fillA = [&](int ic, int s) {
        const char* slab = wslab + (size_t)ic * ASTB;
        #pragma unroll
        for (int j = 0; j < 3; j++) {
            int u = tid + 256 * j;              // 0..767
            int tile = u >> 7, rem = u & 127;   // row=rem>>1, seg=rem&1
            cp_async16(sb + OFF_A + s * ASTB + tile * ATILE + rem * 16,
                       slab + (size_t)u * 16);
        }
    };
    auto ldgX = [&](int ic) {
        #pragma unroll
        for (int r = 0; r < 5; r++) {
            int lp = lng + 32 * r;
            int gl = l0 - 1 + lp;
            bool ok = (lp < 130) && (gl >= 0) && (gl < LDIMC);
            size_t gi = (size_t)(ic * IC + 2 * ipg) * LDIMC + gl;
            xr[r][0] = ok ? __ldg(xb + gi) : 0.f;
            xr[r][1] = ok ? __ldg(xb + gi + LDIMC) : 0.f;
        }
    };
    auto stsX = [&](int s) {
        char* xh = smem + OFF_X + s * XST;
        char* xl = xh + 6240;
        #pragma unroll
        for (int r = 0; r < 5; r++) {
            int lp = lng + 32 * r;
            if (lp < 130) {
                float v0 = xr[r][0], v1 = xr[r][1];
                uint32_t hp = pack_hi(v0, v1);
                float h0 = __uint_as_float(hp << 16);
                float h1 = __uint_as_float(hp & 0xFFFF0000u);
                uint32_t lo = pack_hi(v0 - h0, v1 - h1);
                *(uint32_t*)(xh + lp * 48 + ipg * 4) = hp;
                *(uint32_t*)(xl + lp * 48 + ipg * 4) = lo;
            }
        }
    };

    // ---- prologue: stage 0 ----
    fillA(0, 0); CP_COMMIT();
    ldgX(0);
    CP_WAIT0();
    stsX(0);
    __syncthreads();

    for (int ic = 0; ic < NCH; ic++) {
        const int s = ic & 1;
        if (ic + 1 < NCH) {
            fillA(ic + 1, s ^ 1); CP_COMMIT();
            ldgX(ic + 1);
        }

        const uint32_t aA  = sb + OFF_A + s * ASTB;
        const uint32_t aXH = sb + OFF_X + s * XST;
        const uint32_t aXL = aXH + 6240;
        #pragma unroll
        for (int tap = 0; tap < 3; tap++) {
            uint32_t bh[4][2], bl[4][2];
            #pragma unroll
            for (int np = 0; np < 2; np++) {
                uint32_t rr[4];
                uint32_t rowb = tap + wn * 32 + np * 16 + bro;
                ldsm4(rr, aXH + rowb * 48 + bko);
                bh[np * 2][0] = rr[0]; bh[np * 2][1] = rr[1];
                bh[np * 2 + 1][0] = rr[2]; bh[np * 2 + 1][1] = rr[3];
                ldsm4(rr, aXL + rowb * 48 + bko);
                bl[np * 2][0] = rr[0]; bl[np * 2][1] = rr[1];
                bl[np * 2 + 1][0] = rr[2]; bl[np * 2 + 1][1] = rr[3];
            }
            #pragma unroll
            for (int mf = 0; mf < 2; mf++) {
                uint32_t ah[4], al[4];
                uint32_t rowa = wm * 32 + mf * 16 + aro;
                ldsm4(ah, aA + (tap * 2 + 0) * ATILE + rowa * 32 + ako);
                ldsm4(al, aA + (tap * 2 + 1) * ATILE + rowa * 32 + ako);
                #pragma unroll
                for (int nf = 0; nf < 4; nf++) mma16816(acc[mf][nf], ah, bh[nf]);
                #pragma unroll
                for (int nf = 0; nf < 4; nf++) mma16816(acc[mf][nf], al, bh[nf]);
                #pragma unroll
                for (int nf = 0; nf < 4; nf++) mma16816(acc[mf][nf], ah, bl[nf]);
            }
        }

        if (ic + 1 < NCH) {
            CP_WAIT0();
            stsX(s ^ 1);
        }
        __syncthreads();
    }

    // ---- epilogue: fragments + bias -> global ----
    const float* bagg = (const float*)smem;
    #pragma unroll
    for (int mf = 0; mf < 2; mf++) {
        int rl = wm * 32 + mf * 16 + (lane >> 2);
        float b0 = bagg[rl], b1 = bagg[rl + 8];
        size_t ro0 = ((size_t)(bq * COUTC + o0 + rl)) * LDIMC;
        size_t ro1 = ro0 + 8 * LDIMC;
        #pragma unroll
        for (int nf = 0; nf < 4; nf++) {
            int c = l0 + wn * 32 + nf * 8 + 2 * (lane & 3);
            float2 v0 = make_float2(acc[mf][nf][0] + b0, acc[mf][nf][1] + b0);
            float2 v1 = make_float2(acc[mf][nf][2] + b1, acc[mf][nf][3] + b1);
            *(float2*)(out + ro0 + c) = v0;
            *(float2*)(out + ro1 + c) = v1;
        }
    }
}

// ---------------------------------------------------------------------------
extern "C" void kernel_launch(void* const* d_in, const int* in_sizes, int n_in,
                              void* d_out, int out_size) {
    const float* x      = (const float*)d_in[0];  // (64,256,1024,1)
    const float* cond   = (const float*)d_in[1];  // (64,256)
    const float* w1     = (const float*)d_in[2];  // (64,256)
    const float* w2     = (const float*)d_in[3];  // (4,64)
    const float* weight = (const float*)d_in[4];  // (4,256,256,3,3)
    const float* bias   = (const float*)d_in[5];  // (4,256)
    float* out = (float*)d_out;                   // (64,256,1024,1)

    const int ATT_SMEM = (16384 + 256 + 64 + 4) * 4;
    cudaFuncSetAttribute(att_kernel, cudaFuncAttributeMaxDynamicSharedMemorySize,
                         ATT_SMEM);
    cudaFuncSetAttribute(gemm_kernel, cudaFuncAttributeMaxDynamicSharedMemorySize,
                         SMEMSZ);

    att_kernel<<<NB, 256, ATT_SMEM>>>(cond, w1, w2);
    agg_kernel<<<96, 256>>>(weight);
    dim3 grid(32, NB);
    gemm_kernel<<<grid, 256, SMEMSZ>>>(x, bias, out);
}

// round 15
// speedup vs baseline: 1.3945x; 1.3945x over previous
#include <cuda_runtime.h>
#include <cuda_fp16.h>
#include <cstdint>

// ---------------- problem constants ----------------
#define NB     64
#define CINC   256
#define COUTC  256
#define CSC    256
#define HIDC   64
#define LDIMC  1024
#define TEMPR  30.0f

// ---------------- GEMM tiling ----------------
#define BM   128          // o per block
#define BN   128          // l per block
#define IC   16           // input channels per chunk
#define NCH  16           // CINC / IC

// ---------------- gemm smem map (dynamic) ----------------
// [0,512)            : aggregated bias (128 floats)
// [512, +2*36864)    : A stages; each = 6 tiles (tap x hi/lo) of 128 rows x 48B pitch
// [74240, +2*6240)   : X stages; each = hi(130 x 48B pitch)
#define OFF_A   512
#define ATILE   6144
#define AST     36864
#define OFF_X   74240
#define XST     6240
#define SMEMSZ  86720

// ---------------- device scratch ----------------
__device__ float g_att[NB * 4];
// aggregated weights pre-swizzled into gemm consumption order:
// [b][ot(2)][ic(16)][tap(3)][hl(2)][row(128)][ch(16)] fp16 (hl: hi, residual)
__device__ __align__(16) __half g_w[(size_t)NB * 2 * 16 * 6 * 128 * 16];

// ---------------- helpers ----------------
__device__ __forceinline__ uint32_t smem_u32(const void* p) {
    uint32_t a;
    asm("{ .reg .u64 t; cvta.to.shared.u64 t, %1; cvt.u32.u64 %0, t; }" : "=r"(a) : "l"(p));
    return a;
}
__device__ __forceinline__ void ldsm4(uint32_t (&r)[4], uint32_t addr) {
    asm volatile("ldmatrix.sync.aligned.m8n8.x4.shared.b16 {%0,%1,%2,%3}, [%4];"
                 : "=r"(r[0]), "=r"(r[1]), "=r"(r[2]), "=r"(r[3]) : "r"(addr));
}
__device__ __forceinline__ void mma16816(float (&d)[4], const uint32_t (&a)[4],
                                         const uint32_t (&b)[2]) {
    asm volatile(
        "mma.sync.aligned.m16n8k16.row.col.f32.f16.f16.f32 "
        "{%0,%1,%2,%3}, {%4,%5,%6,%7}, {%8,%9}, {%0,%1,%2,%3};"
        : "+f"(d[0]), "+f"(d[1]), "+f"(d[2]), "+f"(d[3])
        : "r"(a[0]), "r"(a[1]), "r"(a[2]), "r"(a[3]), "r"(b[0]), "r"(b[1]));
}
// pack two f32 into f16x2 (low = v0, high = v1)
__device__ __forceinline__ uint32_t pack_h2(float v0, float v1) {
    uint32_t hp;
    asm("cvt.rn.f16x2.f32 %0, %1, %2;" : "=r"(hp) : "f"(v1), "f"(v0));
    return hp;
}
__device__ __forceinline__ void cp_async16(uint32_t dst, const void* src) {
    asm volatile("cp.async.cg.shared.global [%0], [%1], 16;" :: "r"(dst), "l"(src));
}
#define CP_COMMIT() asm volatile("cp.async.commit_group;" ::: "memory")
#define CP_WAIT0()  asm volatile("cp.async.wait_group 0;" ::: "memory")

// ---------------------------------------------------------------------------
// Kernel 1: routing MLP + softmax -> g_att
// ---------------------------------------------------------------------------
__global__ __launch_bounds__(256) void att_kernel(const float* __restrict__ cond,
                                                  const float* __restrict__ w1,
                                                  const float* __restrict__ w2) {
    int b = blockIdx.x;
    int tid = threadIdx.x;
    int w = tid >> 5, l = tid & 31;
    __shared__ float sc[CSC];
    __shared__ float h[HIDC];
    __shared__ float logits[4];

    sc[tid] = cond[b * CSC + tid];
    __syncthreads();

    #pragma unroll
    for (int jj = 0; jj < 8; jj++) {
        int j = w * 8 + jj;
        const float* r = w1 + j * CSC;
        float a = 0.f;
        #pragma unroll
        for (int q = 0; q < 8; q++) a = fmaf(__ldg(r + l + 32 * q), sc[l + 32 * q], a);
        #pragma unroll
        for (int off = 16; off >= 1; off >>= 1)
            a += __shfl_xor_sync(0xFFFFFFFFu, a, off);
        if (l == 0) h[j] = fmaxf(a, 0.f);
    }
    __syncthreads();

    if (w == 0) {
        #pragma unroll
        for (int j = 0; j < 4; j++) {
            float a = fmaf(__ldg(w2 + j * HIDC + l), h[l],
                           __ldg(w2 + j * HIDC + 32 + l) * h[32 + l]);
            #pragma unroll
            for (int off = 16; off >= 1; off >>= 1)
                a += __shfl_xor_sync(0xFFFFFFFFu, a, off);
            if (l == 0) logits[j] = a / TEMPR;
        }
        __syncwarp();
        if (l == 0) {
            float m = fmaxf(fmaxf(logits[0], logits[1]), fmaxf(logits[2], logits[3]));
            float e[4]; float ssum = 0.f;
            #pragma unroll
            for (int k = 0; k < 4; k++) { e[k] = expf(logits[k] - m); ssum += e[k]; }
            float inv = 1.f / ssum;
            #pragma unroll
            for (int k = 0; k < 4; k++) g_att[b * 4 + k] = e[k] * inv;
        }
    }
}

// ---------------------------------------------------------------------------
// Kernel 2: expert aggregation -> g_w (fp16 hi + fp16 residual), pre-swizzled
// into the gemm's tile consumption order.
// ---------------------------------------------------------------------------
__global__ __launch_bounds__(256) void agg_kernel(const float* __restrict__ weight) {
    __shared__ float satt[NB * 4];
    int tid = threadIdx.x;
    satt[tid] = g_att[tid];   // 256 == NB*4
    __syncthreads();

    int pos = blockIdx.x * 256 + tid;   // 0 .. 98303 = 3*256*128
    int t  = pos >> 15;
    int o  = (pos >> 7) & 255;
    int ip = pos & 127;
    int i  = ip * 2;

    int ot = o >> 7, row = o & 127;
    int icc = i >> 4, ch = i & 15;

    float w[2][4];
    const size_t es = (size_t)COUTC * CINC * 9;
    #pragma unroll
    for (int q = 0; q < 2; q++) {
        size_t base = ((size_t)o * CINC + i + q) * 9 + t * 3 + 1;
        #pragma unroll
        for (int e = 0; e < 4; e++) w[q][e] = __ldg(weight + base + (size_t)e * es);
    }

    for (int b = 0; b < NB; b++) {
        float a0 = satt[b * 4 + 0], a1 = satt[b * 4 + 1];
        float a2 = satt[b * 4 + 2], a3 = satt[b * 4 + 3];
        float v0 = fmaf(a3, w[0][3], fmaf(a2, w[0][2], fmaf(a1, w[0][1], a0 * w[0][0])));
        float v1 = fmaf(a3, w[1][3], fmaf(a2, w[1][2], fmaf(a1, w[1][1], a0 * w[1][0])));
        uint32_t hp = pack_h2(v0, v1);
        __half2 h2 = *reinterpret_cast<__half2*>(&hp);
        float2 hf = __half22float2(h2);
        uint32_t lp = pack_h2(v0 - hf.x, v1 - hf.y);
        // tile index = tap*2 + hl; tile elems = 128 rows x 16 ch = 2048
        size_t base = ((((size_t)(b * 2 + ot) * 16 + icc) * 6) + t * 2) * 2048
                    + row * 16 + ch;
        *reinterpret_cast<uint32_t*>(&g_w[base])        = hp;   // hl=0
        *reinterpret_cast<uint32_t*>(&g_w[base + 2048]) = lp;   // hl=1
    }
}

// ---------------------------------------------------------------------------
// Kernel 3: batched GEMM via mma.sync m16n8k16 fp16 (W hi/lo, x single fp16).
// Double-buffered A (cp.async, coalesced from pre-swizzled g_w) and
// X (register-prefetched LDG, converted post-MMA).  2 CTAs/SM.
// ---------------------------------------------------------------------------
__global__ __launch_bounds__(256, 2)
void gemm_kernel(const float* __restrict__ x,
                 const float* __restrict__ bias,
                 float* __restrict__ out) {
    extern __shared__ char smem[];
    const int tid  = threadIdx.x;
    const int lane = tid & 31, wid = tid >> 5;
    const int wm = wid & 1, wn = wid >> 1;
    const int bq = blockIdx.y;
    const int ot = blockIdx.x & 1;
    const int o0 = ot * BM;
    const int l0 = (blockIdx.x >> 1) * BN;
    const uint32_t sb = smem_u32(smem);

    if (tid < BM) {
        float a0 = g_att[bq * 4 + 0], a1 = g_att[bq * 4 + 1];
        float a2 = g_att[bq * 4 + 2], a3 = g_att[bq * 4 + 3];
        int o = o0 + tid;
        ((float*)smem)[tid] =
            fmaf(a3, bias[3 * COUTC + o], fmaf(a2, bias[2 * COUTC + o],
            fmaf(a1, bias[1 * COUTC + o], a0 * bias[o])));
    }

    float acc[4][4][4];
    #pragma unroll
    for (int mf = 0; mf < 4; mf++)
        #pragma unroll
        for (int nf = 0; nf < 4; nf++)
            #pragma unroll
            for (int q = 0; q < 4; q++) acc[mf][nf][q] = 0.f;

    const uint32_t aro = (lane & 7) + ((lane >> 3) & 1) * 8;
    const uint32_t ako = (lane >> 4) * 16;
    const uint32_t bro = (lane & 7) + ((lane >> 4) & 1) * 8;
    const uint32_t bko = ((lane >> 3) & 1) * 16;

    const float* xb = x + (size_t)bq * CINC * LDIMC;
    // per-(b, ot) weight slab: 16 chunks x 24576 B
    const char* wslab = (const char*)g_w + (size_t)(bq * 2 + ot) * 16 * 24576;
    const int ipg = tid >> 5;   // x-fill: i-pair (0..7)
    const int lng = tid & 31;   // x-fill: lane -> l

    float xr[5][2];

    auto fillA = [&](int ic, int s) {
        const char* slab = wslab + (size_t)ic * 24576;
        #pragma unroll
        for (int j = 0; j < 6; j++) {
            int u = tid + 256 * j;              // 0..1535
            int tile = u >> 8, rem = u & 255;   // row=rem>>1, seg=rem&1
            cp_async16(sb + OFF_A + s * AST + tile * ATILE + (rem >> 1) * 48 + (rem & 1) * 16,
                       slab + (size_t)u * 16);
        }
    };
    auto ldgX = [&](int ic) {
        #pragma unroll
        for (int r = 0; r < 5; r++) {
            int lp = lng + 32 * r;
            int gl = l0 - 1 + lp;
            bool ok = (lp < 130) && (gl >= 0) && (gl < LDIMC);
            size_t gi = (size_t)(ic * IC + 2 * ipg) * LDIMC + gl;
            xr[r][0] = ok ? __ldg(xb + gi) : 0.f;
            xr[r][1] = ok ? __ldg(xb + gi + LDIMC) : 0.f;
        }
    };
    auto stsX = [&](int s) {
        char* xh = smem + OFF_X + s * XST;
        #pragma unroll
        for (int r = 0; r < 5; r++) {
            int lp = lng + 32 * r;
            if (lp < 130)
                *(uint32_t*)(xh + lp * 48 + ipg * 4) = pack_h2(xr[r][0], xr[r][1]);
        }
    };

    // ---- prologue: stage 0 ----
    fillA(0, 0); CP_COMMIT();
    ldgX(0);
    CP_WAIT0();
    stsX(0);
    __syncthreads();

    for (int ic = 0; ic < NCH; ic++) {
        const int s = ic & 1;
        if (ic + 1 < NCH) {
            fillA(ic + 1, s ^ 1); CP_COMMIT();
            ldgX(ic + 1);
        }

        const uint32_t aA  = sb + OFF_A + s * AST;
        const uint32_t aXH = sb + OFF_X + s * XST;
        #pragma unroll
        for (int tap = 0; tap < 3; tap++) {
            uint32_t bh[4][2];
            #pragma unroll
            for (int np = 0; np < 2; np++) {
                uint32_t rr[4];
                uint32_t rowb = tap + wn * 32 + np * 16 + bro;
                ldsm4(rr, aXH + rowb * 48 + bko);
                bh[np * 2][0] = rr[0]; bh[np * 2][1] = rr[1];
                bh[np * 2 + 1][0] = rr[2]; bh[np * 2 + 1][1] = rr[3];
            }
            #pragma unroll
            for (int mf = 0; mf < 4; mf++) {
                uint32_t ah[4], al[4];
                uint32_t rowa = wm * 64 + mf * 16 + aro;
                ldsm4(ah, aA + (tap * 2 + 0) * ATILE + rowa * 48 + ako);
                ldsm4(al, aA + (tap * 2 + 1) * ATILE + rowa * 48 + ako);
                #pragma unroll
                for (int nf = 0; nf < 4; nf++) mma16816(acc[mf][nf], ah, bh[nf]);
                #pragma unroll
                for (int nf = 0; nf < 4; nf++) mma16816(acc[mf][nf], al, bh[nf]);
            }
        }

        if (ic + 1 < NCH) {
            CP_WAIT0();
            stsX(s ^ 1);
        }
        __syncthreads();
    }

    // ---- epilogue: fragments + bias -> global ----
    const float* bagg = (const float*)smem;
    #pragma unroll
    for (int mf = 0; mf < 4; mf++) {
        int rl = wm * 64 + mf * 16 + (lane >> 2);
        float b0 = bagg[rl], b1 = bagg[rl + 8];
        size_t ro0 = ((size_t)(bq * COUTC + o0 + rl)) * LDIMC;
        size_t ro1 = ro0 + 8 * LDIMC;
        #pragma unroll
        for (int nf = 0; nf < 4; nf++) {
            int c = l0 + wn * 32 + nf * 8 + 2 * (lane & 3);
            float2 v0 = make_float2(acc[mf][nf][0] + b0, acc[mf][nf][1] + b0);
            float2 v1 = make_float2(acc[mf][nf][2] + b1, acc[mf][nf][3] + b1);
            *(float2*)(out + ro0 + c) = v0;
            *(float2*)(out + ro1 + c) = v1;
        }
    }
}

// ---------------------------------------------------------------------------
extern "C" void kernel_launch(void* const* d_in, const int* in_sizes, int n_in,
                              void* d_out, int out_size) {
    const float* x      = (const float*)d_in[0];  // (64,256,1024,1)
    const float* cond   = (const float*)d_in[1];  // (64,256)
    const float* w1     = (const float*)d_in[2];  // (64,256)
    const float* w2     = (const float*)d_in[3];  // (4,64)
    const float* weight = (const float*)d_in[4];  // (4,256,256,3,3)
    const float* bias   = (const float*)d_in[5];  // (4,256)
    float* out = (float*)d_out;                   // (64,256,1024,1)

    cudaFuncSetAttribute(gemm_kernel, cudaFuncAttributeMaxDynamicSharedMemorySize,
                         SMEMSZ);

    att_kernel<<<NB, 256>>>(cond, w1, w2);
    agg_kernel<<<384, 256>>>(weight);
    dim3 grid(16, NB);
    gemm_kernel<<<grid, 256, SMEMSZ>>>(x, bias, out);
}